// round 15
// baseline (speedup 1.0000x reference)
#include <cuda_runtime.h>
#include <cuda_bf16.h>
#include <cstdint>

typedef unsigned long long ull;

#define B_TOTAL 131072
#define T_STEPS 30
#define DIN     88
#define H       20
#define NGATE   80

// ================= GEMM (layer-0 input projection, HMMA, persistent) =================
#define M_ROWS   (B_TOTAL * T_STEPS)      // 3932160
#define M_TILE   64
#define N_TILES  (M_ROWS / M_TILE)        // 61440
#define G_GRID   444                      // 3 CTAs/SM persistent
#define G_CTA    128
#define AST      104                      // A smem row stride in bf16 (208 B)
#define CST      84                       // C stage row stride in f32 (336 B)

// smem byte offsets (M_TILE=64)
#define SO_AHI   512                      // 64 x 208 = 13312
#define SO_ALO   (SO_AHI + 13312)         // 13824
#define SO_BFH   (SO_ALO + 13312)         // 27136 : B frag hi, [ko][nf][lane] ull
#define SO_BFL   (SO_BFH + 15360)         // 42496 : B frag lo
#define G_SMEM   (SO_BFL + 15360)         // 57856  (3 CTAs/SM)
#define SO_CSTG  SO_AHI                   // C stage aliases A (dead after MMA)

// 1.26 GB scratch for xg[b*T + t][80] (rec-kernel gate order), fp32
__device__ float g_xg[(size_t)M_ROWS * NGATE];

// ---------------- helpers ----------------
__device__ __forceinline__ void split4(float4 f, ull& hi4, ull& lo4) {
    __nv_bfloat16 hx = __float2bfloat16_rn(f.x);
    __nv_bfloat16 hy = __float2bfloat16_rn(f.y);
    __nv_bfloat16 hz = __float2bfloat16_rn(f.z);
    __nv_bfloat16 hw = __float2bfloat16_rn(f.w);
    __nv_bfloat16 lx = __float2bfloat16_rn(f.x - __bfloat162float(hx));
    __nv_bfloat16 ly = __float2bfloat16_rn(f.y - __bfloat162float(hy));
    __nv_bfloat16 lz = __float2bfloat16_rn(f.z - __bfloat162float(hz));
    __nv_bfloat16 lw = __float2bfloat16_rn(f.w - __bfloat162float(hw));
    hi4 = (ull)__bfloat16_as_ushort(hx) | ((ull)__bfloat16_as_ushort(hy) << 16)
        | ((ull)__bfloat16_as_ushort(hz) << 32) | ((ull)__bfloat16_as_ushort(hw) << 48);
    lo4 = (ull)__bfloat16_as_ushort(lx) | ((ull)__bfloat16_as_ushort(ly) << 16)
        | ((ull)__bfloat16_as_ushort(lz) << 32) | ((ull)__bfloat16_as_ushort(lw) << 48);
}

__device__ __forceinline__ void split2(float2 f, uint32_t& hi2, uint32_t& lo2) {
    __nv_bfloat16 hx = __float2bfloat16_rn(f.x);
    __nv_bfloat16 hy = __float2bfloat16_rn(f.y);
    __nv_bfloat16 lx = __float2bfloat16_rn(f.x - __bfloat162float(hx));
    __nv_bfloat16 ly = __float2bfloat16_rn(f.y - __bfloat162float(hy));
    hi2 = (uint32_t)__bfloat16_as_ushort(hx) | ((uint32_t)__bfloat16_as_ushort(hy) << 16);
    lo2 = (uint32_t)__bfloat16_as_ushort(lx) | ((uint32_t)__bfloat16_as_ushort(ly) << 16);
}

__device__ __forceinline__ void mma16816(float* d,
                                         uint32_t a0, uint32_t a1, uint32_t a2, uint32_t a3,
                                         uint32_t b0, uint32_t b1) {
    asm volatile(
        "mma.sync.aligned.m16n8k16.row.col.f32.bf16.bf16.f32 "
        "{%0,%1,%2,%3}, {%4,%5,%6,%7}, {%8,%9}, {%0,%1,%2,%3};"
        : "+f"(d[0]), "+f"(d[1]), "+f"(d[2]), "+f"(d[3])
        : "r"(a0), "r"(a1), "r"(a2), "r"(a3), "r"(b0), "r"(b1));
}

__device__ __forceinline__ int inv_perm(int n) {
    int g2 = n / 20, r = n % 20, v = r / 5, u = r % 5;
    return v * 20 + g2 * 5 + u;
}

// ---------------- persistent GEMM kernel (EXACT R14 version) ----------------
__global__ void __launch_bounds__(G_CTA, 3)
xg_gemm_kernel(const float* __restrict__ x, const float* __restrict__ Wih0,
               const float* __restrict__ bih0, const float* __restrict__ bhh0)
{
    extern __shared__ char smem[];
    const int tid = threadIdx.x;
    const int warp = tid >> 5, lane = tid & 31;
    const int gid = lane >> 2, tg = lane & 3;

    // ---- one-time: B staged directly in mma-fragment order ----
    if (tid < NGATE) {
        const float4* wr = (const float4*)(Wih0 + tid * DIN);
        float4 wv[22];
        #pragma unroll
        for (int q = 0; q < 22; q++) wv[q] = wr[q];

        const int nf_s = tid >> 3, gid_s = tid & 7;
        #pragma unroll
        for (int ko = 0; ko < 6; ko++) {
            #pragma unroll
            for (int tgs = 0; tgs < 4; tgs++) {
                int p0 = ko * 8 + tgs;
                int p1 = p0 + 4;
                float4 f0 = wv[p0 >> 1];
                float2 e0 = (p0 & 1) ? make_float2(f0.z, f0.w) : make_float2(f0.x, f0.y);
                float2 e1 = make_float2(0.f, 0.f);
                if (p1 < 44) {
                    float4 f1 = wv[p1 >> 1];
                    e1 = (p1 & 1) ? make_float2(f1.z, f1.w) : make_float2(f1.x, f1.y);
                }
                uint32_t h0, l0, h1, l1;
                split2(e0, h0, l0);
                split2(e1, h1, l1);
                int idx = ((ko * 10 + nf_s) * 32 + gid_s * 4 + tgs) * 8;
                *(ull*)(smem + SO_BFH + idx) = (ull)h0 | ((ull)h1 << 32);
                *(ull*)(smem + SO_BFL + idx) = (ull)l0 | ((ull)l1 << 32);
            }
        }
    }

    float2 bias_r[10];
    int ipa[10], ipb[10];
    #pragma unroll
    for (int nf = 0; nf < 10; nf++) {
        int n0 = nf * 8 + tg * 2;
        bias_r[nf] = make_float2(bih0[n0] + bhh0[n0], bih0[n0 + 1] + bhh0[n0 + 1]);
        ipa[nf] = inv_perm(n0);
        ipb[nf] = inv_perm(n0 + 1);
    }

    int tile = blockIdx.x;
    float4 xr[11];
    if (tile < N_TILES) {
        const float4* xp = (const float4*)(x + (size_t)tile * M_TILE * DIN);
        #pragma unroll
        for (int q = 0; q < 11; q++) xr[q] = xp[q * 128 + tid];
    }
    __syncthreads();

    #pragma unroll 1
    for (; tile < N_TILES; tile += G_GRID) {
        #pragma unroll
        for (int q = 0; q < 11; q++) {
            int e = q * 512 + tid * 4;
            int r = e / 88;
            int cc = e - r * 88;
            int addr = r * (AST * 2) + cc * 2;
            ull hi4, lo4;
            split4(xr[q], hi4, lo4);
            *(ull*)(smem + SO_AHI + addr) = hi4;
            *(ull*)(smem + SO_ALO + addr) = lo4;
        }
        if (tid < M_TILE) {
            char* ah = smem + SO_AHI + tid * (AST * 2);
            char* al = smem + SO_ALO + tid * (AST * 2);
            *(ull*)(ah + 176) = 0; *(ull*)(ah + 184) = 0;
            *(ull*)(al + 176) = 0; *(ull*)(al + 184) = 0;
        }
        __syncthreads();

        {
            int nxt = tile + G_GRID;
            if (nxt < N_TILES) {
                const float4* xp = (const float4*)(x + (size_t)nxt * M_TILE * DIN);
                #pragma unroll
                for (int q = 0; q < 11; q++) xr[q] = xp[q * 128 + tid];
            }
        }

        float c[10][4];
        #pragma unroll
        for (int nf = 0; nf < 10; nf++)
            #pragma unroll
            for (int q = 0; q < 4; q++) c[nf][q] = 0.f;

        #pragma unroll 1
        for (int ko6 = 0; ko6 < 6; ko6++) {
            const int kb = (ko6 * 16 + tg * 2) * 2;

            ull bhv[10], blv[10];
            #pragma unroll
            for (int nf = 0; nf < 10; nf++) {
                int idx = ((ko6 * 10 + nf) * 32 + lane) * 8;
                bhv[nf] = *(const ull*)(smem + SO_BFH + idx);
                blv[nf] = *(const ull*)(smem + SO_BFL + idx);
            }
            {
                int m = warp * 16 + gid;
                const char* aph0 = smem + SO_AHI + m * (AST * 2) + kb;
                const char* aph1 = aph0 + 8 * (AST * 2);
                uint32_t ah0 = *(const uint32_t*)(aph0);
                uint32_t ah1 = *(const uint32_t*)(aph1);
                uint32_t ah2 = *(const uint32_t*)(aph0 + 16);
                uint32_t ah3 = *(const uint32_t*)(aph1 + 16);
                const char* apl0 = smem + SO_ALO + m * (AST * 2) + kb;
                const char* apl1 = apl0 + 8 * (AST * 2);
                uint32_t al0 = *(const uint32_t*)(apl0);
                uint32_t al1 = *(const uint32_t*)(apl1);
                uint32_t al2 = *(const uint32_t*)(apl0 + 16);
                uint32_t al3 = *(const uint32_t*)(apl1 + 16);
                #pragma unroll
                for (int nf = 0; nf < 10; nf++) {
                    uint32_t bh0 = (uint32_t)bhv[nf], bh1 = (uint32_t)(bhv[nf] >> 32);
                    uint32_t bl0 = (uint32_t)blv[nf], bl1 = (uint32_t)(blv[nf] >> 32);
                    mma16816(c[nf], ah0, ah1, ah2, ah3, bh0, bh1);
                    mma16816(c[nf], ah0, ah1, ah2, ah3, bl0, bl1);
                    mma16816(c[nf], al0, al1, al2, al3, bh0, bh1);
                }
            }
        }
        __syncthreads();

        float* cw = (float*)(smem + SO_CSTG) + warp * (16 * CST);
        #pragma unroll
        for (int nf = 0; nf < 10; nf++) {
            float bx = bias_r[nf].x, by = bias_r[nf].y;
            cw[ gid      * CST + ipa[nf]] = c[nf][0] + bx;
            cw[ gid      * CST + ipb[nf]] = c[nf][1] + by;
            cw[(gid + 8) * CST + ipa[nf]] = c[nf][2] + bx;
            cw[(gid + 8) * CST + ipb[nf]] = c[nf][3] + by;
        }
        __syncwarp();
        {
            float4* dstw = (float4*)(g_xg + ((size_t)tile * M_TILE + warp * 16) * NGATE);
            #pragma unroll
            for (int i = 0; i < 10; i++) {
                int k = i * 32 + lane;
                int row = k / 20;
                int c4 = k - row * 20;
                float4 v4 = *(const float4*)(cw + row * CST + c4 * 4);
                dstw[k] = v4;
            }
        }
        __syncthreads();
    }
}

// ================= recurrent kernel: v-interleaved weight chunks =================
// smem weight layout per row k: ulonglong2 chunk index cc = c*4 + v  (c=0..4, v=0..3)
// chunk (c,v) holds lane-v outputs o = 4c..4c+3 ; o -> natural gate row (o/5)*20 + v*5 + (o%5)
#define CTA     128
#define HS_STR  33

struct __align__(16) SMR {
    float w0h[H * 80];
    float w1x[H * 80];
    float w1h[H * 80];
    float bias1[80];
    float wfc[2 * H];
    float bfc[2];
    float4 hs0[H * HS_STR];
    float4 hs1[H * HS_STR];
};

__device__ __forceinline__ ull ffma2(ull a, ull b, ull c) {
    ull d;
    asm("fma.rn.f32x2 %0, %1, %2, %3;" : "=l"(d) : "l"(a), "l"(b), "l"(c));
    return d;
}
__device__ __forceinline__ ull pack2(float x) {
    ull r;
    asm("mov.b64 %0, {%1, %1};" : "=l"(r) : "f"(x));
    return r;
}
__device__ __forceinline__ ull packxy(float x, float y) {
    ull r;
    asm("mov.b64 %0, {%1, %2};" : "=l"(r) : "f"(x), "f"(y));
    return r;
}
__device__ __forceinline__ float getf(const ull* acc, int idx) {
    ull v = acc[idx >> 1];
    unsigned u = (idx & 1) ? (unsigned)(v >> 32) : (unsigned)(v & 0xffffffffu);
    return __uint_as_float(u);
}
__device__ __forceinline__ float sig_(float x) {
    return __fdividef(1.0f, 1.0f + __expf(-x));
}
__device__ __forceinline__ float tanh_(float x) {
    float a = fabsf(x);
    float e = __expf(a + a);
    float r = 1.0f - __fdividef(2.0f, e + 1.0f);
    return copysignf(r, x);
}
// w points at chunk (c=0) of this lane's v; chunks at stride 4 (64B block per (k,c))
__device__ __forceinline__ void accum4(ull* a, const ulonglong2* __restrict__ w,
                                       ull x0, ull x1, ull x2, ull x3) {
    #pragma unroll
    for (int c = 0; c < 5; c++) {
        ulonglong2 wc = w[c * 4];
        a[ 0 + 2*c]   = ffma2(wc.x, x0, a[ 0 + 2*c]);
        a[ 0 + 2*c+1] = ffma2(wc.y, x0, a[ 0 + 2*c+1]);
        a[10 + 2*c]   = ffma2(wc.x, x1, a[10 + 2*c]);
        a[10 + 2*c+1] = ffma2(wc.y, x1, a[10 + 2*c+1]);
        a[20 + 2*c]   = ffma2(wc.x, x2, a[20 + 2*c]);
        a[20 + 2*c+1] = ffma2(wc.y, x2, a[20 + 2*c+1]);
        a[30 + 2*c]   = ffma2(wc.x, x3, a[30 + 2*c]);
        a[30 + 2*c+1] = ffma2(wc.y, x3, a[30 + 2*c+1]);
    }
}

__global__ void __launch_bounds__(CTA, 3) lstm2_rec_kernel(
    const float* __restrict__ Whh0,
    const float* __restrict__ Wih1, const float* __restrict__ Whh1,
    const float* __restrict__ bih1, const float* __restrict__ bhh1,
    const float* __restrict__ Wfc,  const float* __restrict__ bfc,
    float* __restrict__ out)
{
    extern __shared__ unsigned char smraw[];
    SMR* sm = reinterpret_cast<SMR*>(smraw);
    const int tid = threadIdx.x;

    // ---- stage weights, v-interleaved chunk layout ----
    #pragma unroll 1
    for (int idx = tid; idx < H * 80; idx += CTA) {
        int d = idx / 80, f = idx - d * 80;
        int cc = f >> 2, j = f & 3;
        int c = cc >> 2, v = cc & 3;
        int o = c * 4 + j;
        int row = (o / 5) * 20 + v * 5 + (o % 5);
        sm->w0h[idx] = Whh0[row * H + d];
        sm->w1x[idx] = Wih1[row * H + d];
        sm->w1h[idx] = Whh1[row * H + d];
    }
    if (tid < 80) {
        int f = tid;
        int cc = f >> 2, j = f & 3;
        int c = cc >> 2, v = cc & 3;
        int o = c * 4 + j;
        int row = (o / 5) * 20 + v * 5 + (o % 5);
        sm->bias1[tid] = bih1[row] + bhh1[row];
    }
    if (tid < 2 * H) sm->wfc[tid] = Wfc[tid];
    if (tid < 2)     sm->bfc[tid] = bfc[tid];

    const int g = tid >> 2;
    const int v = tid & 3;

    #pragma unroll
    for (int ul = 0; ul < 5; ul++) {
        sm->hs0[(v * 5 + ul) * HS_STR + g] = make_float4(0.f, 0.f, 0.f, 0.f);
        sm->hs1[(v * 5 + ul) * HS_STR + g] = make_float4(0.f, 0.f, 0.f, 0.f);
    }
    __syncthreads();

    const int bg = blockIdx.x * CTA + g * 4;
    const float* xg0 = g_xg + ((size_t)(bg + 0) * T_STEPS) * NGATE + v * 20;
    const float* xg1 = g_xg + ((size_t)(bg + 1) * T_STEPS) * NGATE + v * 20;
    const float* xg2 = g_xg + ((size_t)(bg + 2) * T_STEPS) * NGATE + v * 20;
    const float* xg3 = g_xg + ((size_t)(bg + 3) * T_STEPS) * NGATE + v * 20;

    const ulonglong2* w0h = reinterpret_cast<const ulonglong2*>(sm->w0h) + v;
    const ulonglong2* w1x = reinterpret_cast<const ulonglong2*>(sm->w1x) + v;
    const ulonglong2* w1h = reinterpret_cast<const ulonglong2*>(sm->w1h) + v;
    const ulonglong2* bias1 = reinterpret_cast<const ulonglong2*>(sm->bias1) + v;
    float4* hs0 = sm->hs0;
    float4* hs1 = sm->hs1;

    float c0[20], c1[20];
    #pragma unroll
    for (int i = 0; i < 20; i++) { c0[i] = 0.f; c1[i] = 0.f; }

    ull a[40];

    #pragma unroll 1
    for (int t = 0; t < T_STEPS; t++) {
        // ===== layer 0: acc = xg (bias folded in GEMM) =====
        {
            const float4* p0 = (const float4*)(xg0 + t * NGATE);
            const float4* p1 = (const float4*)(xg1 + t * NGATE);
            const float4* p2 = (const float4*)(xg2 + t * NGATE);
            const float4* p3 = (const float4*)(xg3 + t * NGATE);
            #pragma unroll
            for (int u = 0; u < 5; u++) {
                float4 q0 = p0[u], q1 = p1[u], q2 = p2[u], q3 = p3[u];
                a[      2*u] = packxy(q0.x, q0.y); a[      2*u+1] = packxy(q0.z, q0.w);
                a[10 +  2*u] = packxy(q1.x, q1.y); a[10 +  2*u+1] = packxy(q1.z, q1.w);
                a[20 +  2*u] = packxy(q2.x, q2.y); a[20 +  2*u+1] = packxy(q2.z, q2.w);
                a[30 +  2*u] = packxy(q3.x, q3.y); a[30 +  2*u+1] = packxy(q3.z, q3.w);
            }
        }
        #pragma unroll 4
        for (int k = 0; k < H; k++) {
            float4 hv = hs0[k * HS_STR + g];
            accum4(a, w0h + k * 20,
                   pack2(hv.x), pack2(hv.y), pack2(hv.z), pack2(hv.w));
        }
        #pragma unroll
        for (int ul = 0; ul < 5; ul++) {
            float hv[4];
            #pragma unroll
            for (int e = 0; e < 4; e++) {
                const ull* ae = a + e * 10;
                float iv = sig_ (getf(ae,      ul));
                float fv = sig_ (getf(ae,  5 + ul));
                float gv = tanh_(getf(ae, 10 + ul));
                float ov = sig_ (getf(ae, 15 + ul));
                float cn = fv * c0[e*5 + ul] + iv * gv;
                c0[e*5 + ul] = cn;
                hv[e] = ov * tanh_(cn);
            }
            hs0[(v * 5 + ul) * HS_STR + g] = make_float4(hv[0], hv[1], hv[2], hv[3]);
        }
        __syncwarp();

        // ===== layer 1 =====
        #pragma unroll
        for (int c = 0; c < 5; c++) {
            ulonglong2 bb = bias1[c * 4];
            a[2*c] = bb.x; a[2*c+1] = bb.y;
            a[10+2*c] = bb.x; a[10+2*c+1] = bb.y;
            a[20+2*c] = bb.x; a[20+2*c+1] = bb.y;
            a[30+2*c] = bb.x; a[30+2*c+1] = bb.y;
        }
        #pragma unroll 4
        for (int k = 0; k < H; k++) {
            float4 hv = hs0[k * HS_STR + g];
            accum4(a, w1x + k * 20,
                   pack2(hv.x), pack2(hv.y), pack2(hv.z), pack2(hv.w));
        }
        #pragma unroll 4
        for (int k = 0; k < H; k++) {
            float4 hv = hs1[k * HS_STR + g];
            accum4(a, w1h + k * 20,
                   pack2(hv.x), pack2(hv.y), pack2(hv.z), pack2(hv.w));
        }
        #pragma unroll
        for (int ul = 0; ul < 5; ul++) {
            float hv[4];
            #pragma unroll
            for (int e = 0; e < 4; e++) {
                const ull* ae = a + e * 10;
                float iv = sig_ (getf(ae,      ul));
                float fv = sig_ (getf(ae,  5 + ul));
                float gv = tanh_(getf(ae, 10 + ul));
                float ov = sig_ (getf(ae, 15 + ul));
                float cn = fv * c1[e*5 + ul] + iv * gv;
                c1[e*5 + ul] = cn;
                hv[e] = ov * tanh_(cn);
            }
            hs1[(v * 5 + ul) * HS_STR + g] = make_float4(hv[0], hv[1], hv[2], hv[3]);
        }
        __syncwarp();
    }

    // ---- FC + softmax(2) ----
    float l0 = sm->bfc[0], l1 = sm->bfc[1];
    #pragma unroll
    for (int k = 0; k < H; k++) {
        float4 hq = hs1[k * HS_STR + g];
        float hk = (v == 0) ? hq.x : (v == 1) ? hq.y : (v == 2) ? hq.z : hq.w;
        l0 += sm->wfc[k]     * hk;
        l1 += sm->wfc[H + k] * hk;
    }
    float p0 = sig_(l0 - l1);
    reinterpret_cast<float2*>(out)[bg + v] = make_float2(p0, 1.0f - p0);
}

// ---------------- launch ----------------
extern "C" void kernel_launch(void* const* d_in, const int* in_sizes, int n_in,
                              void* d_out, int out_size) {
    const float* x    = (const float*)d_in[0];
    const float* Wih0 = (const float*)d_in[1];
    const float* Whh0 = (const float*)d_in[2];
    const float* bih0 = (const float*)d_in[3];
    const float* bhh0 = (const float*)d_in[4];
    const float* Wih1 = (const float*)d_in[5];
    const float* Whh1 = (const float*)d_in[6];
    const float* bih1 = (const float*)d_in[7];
    const float* bhh1 = (const float*)d_in[8];
    const float* Wfc  = (const float*)d_in[9];
    const float* bfc  = (const float*)d_in[10];
    float* out = (float*)d_out;

    cudaFuncSetAttribute(xg_gemm_kernel, cudaFuncAttributeMaxDynamicSharedMemorySize, G_SMEM);
    xg_gemm_kernel<<<G_GRID, G_CTA, G_SMEM>>>(x, Wih0, bih0, bhh0);

    const size_t smem2 = sizeof(SMR);
    cudaFuncSetAttribute(lstm2_rec_kernel, cudaFuncAttributeMaxDynamicSharedMemorySize, (int)smem2);
    lstm2_rec_kernel<<<B_TOTAL / CTA, CTA, smem2>>>(
        Whh0, Wih1, Whh1, bih1, bhh1, Wfc, bfc, out);
}

// round 16
// speedup vs baseline: 1.0378x; 1.0378x over previous
#include <cuda_runtime.h>
#include <cuda_bf16.h>
#include <cstdint>

typedef unsigned long long ull;

#define B_TOTAL 131072
#define T_STEPS 30
#define DIN     88
#define H       20
#define NGATE   80

// ================= GEMM (layer-0 input projection, HMMA, persistent) =================
#define M_ROWS   (B_TOTAL * T_STEPS)      // 3932160
#define M_TILE   64
#define N_TILES  (M_ROWS / M_TILE)        // 61440
#define G_GRID   444                      // 3 CTAs/SM persistent
#define G_CTA    128
#define AST      104                      // A smem row stride in bf16 (208 B)
#define CST      84                       // C stage row stride in f32 (336 B)

// smem byte offsets (M_TILE=64)
#define SO_AHI   512                      // 64 x 208 = 13312
#define SO_ALO   (SO_AHI + 13312)         // 13824
#define SO_BFH   (SO_ALO + 13312)         // 27136 : B frag hi, [ko][nf][lane] ull
#define SO_BFL   (SO_BFH + 15360)         // 42496 : B frag lo
#define G_SMEM   (SO_BFL + 15360)         // 57856  (3 CTAs/SM)
#define SO_CSTG  SO_AHI                   // C stage aliases A (dead after MMA)

// 1.26 GB scratch, rec-coalesced layout:
// float4 index = ((b>>7)*30 + t)*2560 + q*128 + lane
//   where lane = (b&127 >>2)*4 + v, q = (b&3)*5 + u  holds chunk (v*5+u) of elem b
__device__ float g_xg[(size_t)M_ROWS * NGATE];

// ---------------- helpers ----------------
__device__ __forceinline__ void split4(float4 f, ull& hi4, ull& lo4) {
    __nv_bfloat16 hx = __float2bfloat16_rn(f.x);
    __nv_bfloat16 hy = __float2bfloat16_rn(f.y);
    __nv_bfloat16 hz = __float2bfloat16_rn(f.z);
    __nv_bfloat16 hw = __float2bfloat16_rn(f.w);
    __nv_bfloat16 lx = __float2bfloat16_rn(f.x - __bfloat162float(hx));
    __nv_bfloat16 ly = __float2bfloat16_rn(f.y - __bfloat162float(hy));
    __nv_bfloat16 lz = __float2bfloat16_rn(f.z - __bfloat162float(hz));
    __nv_bfloat16 lw = __float2bfloat16_rn(f.w - __bfloat162float(hw));
    hi4 = (ull)__bfloat16_as_ushort(hx) | ((ull)__bfloat16_as_ushort(hy) << 16)
        | ((ull)__bfloat16_as_ushort(hz) << 32) | ((ull)__bfloat16_as_ushort(hw) << 48);
    lo4 = (ull)__bfloat16_as_ushort(lx) | ((ull)__bfloat16_as_ushort(ly) << 16)
        | ((ull)__bfloat16_as_ushort(lz) << 32) | ((ull)__bfloat16_as_ushort(lw) << 48);
}

__device__ __forceinline__ void split2(float2 f, uint32_t& hi2, uint32_t& lo2) {
    __nv_bfloat16 hx = __float2bfloat16_rn(f.x);
    __nv_bfloat16 hy = __float2bfloat16_rn(f.y);
    __nv_bfloat16 lx = __float2bfloat16_rn(f.x - __bfloat162float(hx));
    __nv_bfloat16 ly = __float2bfloat16_rn(f.y - __bfloat162float(hy));
    hi2 = (uint32_t)__bfloat16_as_ushort(hx) | ((uint32_t)__bfloat16_as_ushort(hy) << 16);
    lo2 = (uint32_t)__bfloat16_as_ushort(lx) | ((uint32_t)__bfloat16_as_ushort(ly) << 16);
}

__device__ __forceinline__ void mma16816(float* d,
                                         uint32_t a0, uint32_t a1, uint32_t a2, uint32_t a3,
                                         uint32_t b0, uint32_t b1) {
    asm volatile(
        "mma.sync.aligned.m16n8k16.row.col.f32.bf16.bf16.f32 "
        "{%0,%1,%2,%3}, {%4,%5,%6,%7}, {%8,%9}, {%0,%1,%2,%3};"
        : "+f"(d[0]), "+f"(d[1]), "+f"(d[2]), "+f"(d[3])
        : "r"(a0), "r"(a1), "r"(a2), "r"(a3), "r"(b0), "r"(b1));
}

__device__ __forceinline__ int inv_perm(int n) {
    int g2 = n / 20, r = n % 20, v = r / 5, u = r % 5;
    return v * 20 + g2 * 5 + u;
}

// ---------------- persistent GEMM kernel ----------------
__global__ void __launch_bounds__(G_CTA, 3)
xg_gemm_kernel(const float* __restrict__ x, const float* __restrict__ Wih0,
               const float* __restrict__ bih0, const float* __restrict__ bhh0)
{
    extern __shared__ char smem[];
    const int tid = threadIdx.x;
    const int warp = tid >> 5, lane = tid & 31;
    const int gid = lane >> 2, tg = lane & 3;

    // ---- one-time: B staged directly in mma-fragment order ----
    if (tid < NGATE) {
        const float4* wr = (const float4*)(Wih0 + tid * DIN);
        float4 wv[22];
        #pragma unroll
        for (int q = 0; q < 22; q++) wv[q] = wr[q];

        const int nf_s = tid >> 3, gid_s = tid & 7;
        #pragma unroll
        for (int ko = 0; ko < 6; ko++) {
            #pragma unroll
            for (int tgs = 0; tgs < 4; tgs++) {
                int p0 = ko * 8 + tgs;
                int p1 = p0 + 4;
                float4 f0 = wv[p0 >> 1];
                float2 e0 = (p0 & 1) ? make_float2(f0.z, f0.w) : make_float2(f0.x, f0.y);
                float2 e1 = make_float2(0.f, 0.f);
                if (p1 < 44) {
                    float4 f1 = wv[p1 >> 1];
                    e1 = (p1 & 1) ? make_float2(f1.z, f1.w) : make_float2(f1.x, f1.y);
                }
                uint32_t h0, l0, h1, l1;
                split2(e0, h0, l0);
                split2(e1, h1, l1);
                int idx = ((ko * 10 + nf_s) * 32 + gid_s * 4 + tgs) * 8;
                *(ull*)(smem + SO_BFH + idx) = (ull)h0 | ((ull)h1 << 32);
                *(ull*)(smem + SO_BFL + idx) = (ull)l0 | ((ull)l1 << 32);
            }
        }
    }

    float2 bias_r[10];
    int ipa[10], ipb[10];
    #pragma unroll
    for (int nf = 0; nf < 10; nf++) {
        int n0 = nf * 8 + tg * 2;
        bias_r[nf] = make_float2(bih0[n0] + bhh0[n0], bih0[n0 + 1] + bhh0[n0 + 1]);
        ipa[nf] = inv_perm(n0);
        ipb[nf] = inv_perm(n0 + 1);
    }

    int tile = blockIdx.x;
    float4 xr[11];
    if (tile < N_TILES) {
        const float4* xp = (const float4*)(x + (size_t)tile * M_TILE * DIN);
        #pragma unroll
        for (int q = 0; q < 11; q++) xr[q] = xp[q * 128 + tid];
    }
    __syncthreads();

    #pragma unroll 1
    for (; tile < N_TILES; tile += G_GRID) {
        #pragma unroll
        for (int q = 0; q < 11; q++) {
            int e = q * 512 + tid * 4;
            int r = e / 88;
            int cc = e - r * 88;
            int addr = r * (AST * 2) + cc * 2;
            ull hi4, lo4;
            split4(xr[q], hi4, lo4);
            *(ull*)(smem + SO_AHI + addr) = hi4;
            *(ull*)(smem + SO_ALO + addr) = lo4;
        }
        if (tid < M_TILE) {
            char* ah = smem + SO_AHI + tid * (AST * 2);
            char* al = smem + SO_ALO + tid * (AST * 2);
            *(ull*)(ah + 176) = 0; *(ull*)(ah + 184) = 0;
            *(ull*)(al + 176) = 0; *(ull*)(al + 184) = 0;
        }
        __syncthreads();

        {
            int nxt = tile + G_GRID;
            if (nxt < N_TILES) {
                const float4* xp = (const float4*)(x + (size_t)nxt * M_TILE * DIN);
                #pragma unroll
                for (int q = 0; q < 11; q++) xr[q] = xp[q * 128 + tid];
            }
        }

        float c[10][4];
        #pragma unroll
        for (int nf = 0; nf < 10; nf++)
            #pragma unroll
            for (int q = 0; q < 4; q++) c[nf][q] = 0.f;

        #pragma unroll 1
        for (int ko6 = 0; ko6 < 6; ko6++) {
            const int kb = (ko6 * 16 + tg * 2) * 2;

            ull bhv[10], blv[10];
            #pragma unroll
            for (int nf = 0; nf < 10; nf++) {
                int idx = ((ko6 * 10 + nf) * 32 + lane) * 8;
                bhv[nf] = *(const ull*)(smem + SO_BFH + idx);
                blv[nf] = *(const ull*)(smem + SO_BFL + idx);
            }
            {
                int m = warp * 16 + gid;
                const char* aph0 = smem + SO_AHI + m * (AST * 2) + kb;
                const char* aph1 = aph0 + 8 * (AST * 2);
                uint32_t ah0 = *(const uint32_t*)(aph0);
                uint32_t ah1 = *(const uint32_t*)(aph1);
                uint32_t ah2 = *(const uint32_t*)(aph0 + 16);
                uint32_t ah3 = *(const uint32_t*)(aph1 + 16);
                const char* apl0 = smem + SO_ALO + m * (AST * 2) + kb;
                const char* apl1 = apl0 + 8 * (AST * 2);
                uint32_t al0 = *(const uint32_t*)(apl0);
                uint32_t al1 = *(const uint32_t*)(apl1);
                uint32_t al2 = *(const uint32_t*)(apl0 + 16);
                uint32_t al3 = *(const uint32_t*)(apl1 + 16);
                #pragma unroll
                for (int nf = 0; nf < 10; nf++) {
                    uint32_t bh0 = (uint32_t)bhv[nf], bh1 = (uint32_t)(bhv[nf] >> 32);
                    uint32_t bl0 = (uint32_t)blv[nf], bl1 = (uint32_t)(blv[nf] >> 32);
                    mma16816(c[nf], ah0, ah1, ah2, ah3, bh0, bh1);
                    mma16816(c[nf], ah0, ah1, ah2, ah3, bl0, bl1);
                    mma16816(c[nf], al0, al1, al2, al3, bh0, bh1);
                }
            }
        }
        __syncthreads();

        // ---- epilogue: frags -> cstg PERMUTED + bias ----
        float* cw = (float*)(smem + SO_CSTG) + warp * (16 * CST);
        #pragma unroll
        for (int nf = 0; nf < 10; nf++) {
            float bx = bias_r[nf].x, by = bias_r[nf].y;
            cw[ gid      * CST + ipa[nf]] = c[nf][0] + bx;
            cw[ gid      * CST + ipb[nf]] = c[nf][1] + by;
            cw[(gid + 8) * CST + ipa[nf]] = c[nf][2] + bx;
            cw[(gid + 8) * CST + ipb[nf]] = c[nf][3] + by;
        }
        __syncwarp();
        // ---- stream-out to rec-coalesced layout (64B clusters per row) ----
        {
            const int mbase = tile * M_TILE + warp * 16;
            #pragma unroll
            for (int i = 0; i < 10; i++) {
                int s = i * 32 + lane;          // 0..319 = 16 rows x 20 float4
                int r = s / 20, j = s - r * 20;
                int u = j >> 2, vv = j & 3;     // vv fastest -> 64B-contiguous dst
                float4 v4 = *(const float4*)(cw + r * CST + (vv * 5 + u) * 4);
                int m = mbase + r;
                int b = m / 30, t = m - b * 30;
                int e128 = b & 127;
                size_t dst = ((size_t)(b >> 7) * 30 + t) * 2560
                           + (size_t)(((e128 & 3) * 5 + u) * 128 + (e128 >> 2) * 4 + vv);
                ((float4*)g_xg)[dst] = v4;
            }
        }
        __syncthreads();
    }
}

// ================= recurrent kernel (R12 math; coalesced xg reads) =================
#define CTA     128
#define HS_STR  33

struct __align__(16) SMR {
    float w0h[H * 80];
    float w1x[H * 80];
    float w1h[H * 80];
    float bias1[80];
    float wfc[2 * H];
    float bfc[2];
    float4 hs0[H * HS_STR];
    float4 hs1[H * HS_STR];
};

__device__ __forceinline__ ull ffma2(ull a, ull b, ull c) {
    ull d;
    asm("fma.rn.f32x2 %0, %1, %2, %3;" : "=l"(d) : "l"(a), "l"(b), "l"(c));
    return d;
}
__device__ __forceinline__ ull pack2(float x) {
    ull r;
    asm("mov.b64 %0, {%1, %1};" : "=l"(r) : "f"(x));
    return r;
}
__device__ __forceinline__ ull packxy(float x, float y) {
    ull r;
    asm("mov.b64 %0, {%1, %2};" : "=l"(r) : "f"(x), "f"(y));
    return r;
}
__device__ __forceinline__ float getf(const ull* acc, int idx) {
    ull v = acc[idx >> 1];
    unsigned u = (idx & 1) ? (unsigned)(v >> 32) : (unsigned)(v & 0xffffffffu);
    return __uint_as_float(u);
}
__device__ __forceinline__ float sig_(float x) {
    return __fdividef(1.0f, 1.0f + __expf(-x));
}
__device__ __forceinline__ float tanh_(float x) {
    float a = fabsf(x);
    float e = __expf(a + a);
    float r = 1.0f - __fdividef(2.0f, e + 1.0f);
    return copysignf(r, x);
}
__device__ __forceinline__ void accum4(ull* a, const ulonglong2* __restrict__ w,
                                       ull x0, ull x1, ull x2, ull x3) {
    #pragma unroll
    for (int c = 0; c < 5; c++) {
        ulonglong2 wc = w[c];
        a[ 0 + 2*c]   = ffma2(wc.x, x0, a[ 0 + 2*c]);
        a[ 0 + 2*c+1] = ffma2(wc.y, x0, a[ 0 + 2*c+1]);
        a[10 + 2*c]   = ffma2(wc.x, x1, a[10 + 2*c]);
        a[10 + 2*c+1] = ffma2(wc.y, x1, a[10 + 2*c+1]);
        a[20 + 2*c]   = ffma2(wc.x, x2, a[20 + 2*c]);
        a[20 + 2*c+1] = ffma2(wc.y, x2, a[20 + 2*c+1]);
        a[30 + 2*c]   = ffma2(wc.x, x3, a[30 + 2*c]);
        a[30 + 2*c+1] = ffma2(wc.y, x3, a[30 + 2*c+1]);
    }
}

__global__ void __launch_bounds__(CTA, 3) lstm2_rec_kernel(
    const float* __restrict__ Whh0,
    const float* __restrict__ Wih1, const float* __restrict__ Whh1,
    const float* __restrict__ bih1, const float* __restrict__ bhh1,
    const float* __restrict__ Wfc,  const float* __restrict__ bfc,
    float* __restrict__ out)
{
    extern __shared__ unsigned char smraw[];
    SMR* sm = reinterpret_cast<SMR*>(smraw);
    const int tid = threadIdx.x;

    #pragma unroll 1
    for (int idx = tid; idx < H * 80; idx += CTA) {
        int d = idx / 80, rem = idx - d * 80;
        int v = rem / 20, o = rem - v * 20;
        int row = (o / 5) * 20 + v * 5 + (o % 5);
        sm->w0h[idx] = Whh0[row * H + d];
        sm->w1x[idx] = Wih1[row * H + d];
        sm->w1h[idx] = Whh1[row * H + d];
    }
    if (tid < 80) {
        int v = tid / 20, o = tid - v * 20;
        int row = (o / 5) * 20 + v * 5 + (o % 5);
        sm->bias1[tid] = bih1[row] + bhh1[row];
    }
    if (tid < 2 * H) sm->wfc[tid] = Wfc[tid];
    if (tid < 2)     sm->bfc[tid] = bfc[tid];

    const int g = tid >> 2;
    const int v = tid & 3;

    #pragma unroll
    for (int ul = 0; ul < 5; ul++) {
        sm->hs0[(v * 5 + ul) * HS_STR + g] = make_float4(0.f, 0.f, 0.f, 0.f);
        sm->hs1[(v * 5 + ul) * HS_STR + g] = make_float4(0.f, 0.f, 0.f, 0.f);
    }
    __syncthreads();

    const int bg = blockIdx.x * CTA + g * 4;
    // coalesced xg: thread's float4 at blk(t)*2560 + (e*5+u)*128 + tid
    const float4* xgp = (const float4*)g_xg + (size_t)blockIdx.x * T_STEPS * 2560 + tid;

    const ulonglong2* w0h = reinterpret_cast<const ulonglong2*>(sm->w0h);
    const ulonglong2* w1x = reinterpret_cast<const ulonglong2*>(sm->w1x);
    const ulonglong2* w1h = reinterpret_cast<const ulonglong2*>(sm->w1h);
    const ulonglong2* bias1 = reinterpret_cast<const ulonglong2*>(sm->bias1) + v * 5;
    float4* hs0 = sm->hs0;
    float4* hs1 = sm->hs1;

    float c0[20], c1[20];
    #pragma unroll
    for (int i = 0; i < 20; i++) { c0[i] = 0.f; c1[i] = 0.f; }

    ull a[40];

    #pragma unroll 1
    for (int t = 0; t < T_STEPS; t++) {
        // ===== layer 0: acc = xg (bias folded in GEMM), fully coalesced =====
        {
            const float4* pt = xgp + (size_t)t * 2560;
            #pragma unroll
            for (int e = 0; e < 4; e++) {
                #pragma unroll
                for (int u = 0; u < 5; u++) {
                    float4 f = pt[(e * 5 + u) * 128];
                    a[e * 10 + 2 * u]     = packxy(f.x, f.y);
                    a[e * 10 + 2 * u + 1] = packxy(f.z, f.w);
                }
            }
        }
        #pragma unroll 4
        for (int k = 0; k < H; k++) {
            float4 hv = hs0[k * HS_STR + g];
            accum4(a, w0h + k * 20 + v * 5,
                   pack2(hv.x), pack2(hv.y), pack2(hv.z), pack2(hv.w));
        }
        #pragma unroll
        for (int ul = 0; ul < 5; ul++) {
            float hv[4];
            #pragma unroll
            for (int e = 0; e < 4; e++) {
                const ull* ae = a + e * 10;
                float iv = sig_ (getf(ae,      ul));
                float fv = sig_ (getf(ae,  5 + ul));
                float gv = tanh_(getf(ae, 10 + ul));
                float ov = sig_ (getf(ae, 15 + ul));
                float cn = fv * c0[e*5 + ul] + iv * gv;
                c0[e*5 + ul] = cn;
                hv[e] = ov * tanh_(cn);
            }
            hs0[(v * 5 + ul) * HS_STR + g] = make_float4(hv[0], hv[1], hv[2], hv[3]);
        }
        __syncwarp();

        // ===== layer 1 =====
        #pragma unroll
        for (int c = 0; c < 5; c++) {
            ulonglong2 bb = bias1[c];
            a[2*c] = bb.x; a[2*c+1] = bb.y;
            a[10+2*c] = bb.x; a[10+2*c+1] = bb.y;
            a[20+2*c] = bb.x; a[20+2*c+1] = bb.y;
            a[30+2*c] = bb.x; a[30+2*c+1] = bb.y;
        }
        #pragma unroll 4
        for (int k = 0; k < H; k++) {
            float4 hv = hs0[k * HS_STR + g];
            accum4(a, w1x + k * 20 + v * 5,
                   pack2(hv.x), pack2(hv.y), pack2(hv.z), pack2(hv.w));
        }
        #pragma unroll 4
        for (int k = 0; k < H; k++) {
            float4 hv = hs1[k * HS_STR + g];
            accum4(a, w1h + k * 20 + v * 5,
                   pack2(hv.x), pack2(hv.y), pack2(hv.z), pack2(hv.w));
        }
        #pragma unroll
        for (int ul = 0; ul < 5; ul++) {
            float hv[4];
            #pragma unroll
            for (int e = 0; e < 4; e++) {
                const ull* ae = a + e * 10;
                float iv = sig_ (getf(ae,      ul));
                float fv = sig_ (getf(ae,  5 + ul));
                float gv = tanh_(getf(ae, 10 + ul));
                float ov = sig_ (getf(ae, 15 + ul));
                float cn = fv * c1[e*5 + ul] + iv * gv;
                c1[e*5 + ul] = cn;
                hv[e] = ov * tanh_(cn);
            }
            hs1[(v * 5 + ul) * HS_STR + g] = make_float4(hv[0], hv[1], hv[2], hv[3]);
        }
        __syncwarp();
    }

    // ---- FC + softmax(2) ----
    float l0 = sm->bfc[0], l1 = sm->bfc[1];
    #pragma unroll
    for (int k = 0; k < H; k++) {
        float4 hq = hs1[k * HS_STR + g];
        float hk = (v == 0) ? hq.x : (v == 1) ? hq.y : (v == 2) ? hq.z : hq.w;
        l0 += sm->wfc[k]     * hk;
        l1 += sm->wfc[H + k] * hk;
    }
    float p0 = sig_(l0 - l1);
    reinterpret_cast<float2*>(out)[bg + v] = make_float2(p0, 1.0f - p0);
}

// ---------------- launch ----------------
extern "C" void kernel_launch(void* const* d_in, const int* in_sizes, int n_in,
                              void* d_out, int out_size) {
    const float* x    = (const float*)d_in[0];
    const float* Wih0 = (const float*)d_in[1];
    const float* Whh0 = (const float*)d_in[2];
    const float* bih0 = (const float*)d_in[3];
    const float* bhh0 = (const float*)d_in[4];
    const float* Wih1 = (const float*)d_in[5];
    const float* Whh1 = (const float*)d_in[6];
    const float* bih1 = (const float*)d_in[7];
    const float* bhh1 = (const float*)d_in[8];
    const float* Wfc  = (const float*)d_in[9];
    const float* bfc  = (const float*)d_in[10];
    float* out = (float*)d_out;

    cudaFuncSetAttribute(xg_gemm_kernel, cudaFuncAttributeMaxDynamicSharedMemorySize, G_SMEM);
    xg_gemm_kernel<<<G_GRID, G_CTA, G_SMEM>>>(x, Wih0, bih0, bhh0);

    const size_t smem2 = sizeof(SMR);
    cudaFuncSetAttribute(lstm2_rec_kernel, cudaFuncAttributeMaxDynamicSharedMemorySize, (int)smem2);
    lstm2_rec_kernel<<<B_TOTAL / CTA, CTA, smem2>>>(
        Whh0, Wih1, Whh1, bih1, bhh1, Wfc, bfc, out);
}